// round 13
// baseline (speedup 1.0000x reference)
#include <cuda_runtime.h>
#include <cuda_bf16.h>
#include <math.h>

// RoPE: x[B=16, S=8192, D=128] fp32, interleaved pairs, pos = arange(S)
// (token_positions is ignored by the reference).
//
// R9 structure, but input loads go through cp.async (LDGSTS) into smem:
// MLP=4 per thread WITHOUT holding 16 registers of in-flight data.
// Regs drop -> 8 CTAs/SM (full occupancy) -> ~2x outstanding loads per SM.
//   - 4x cp.async.cg 16B per thread -> sbuf, commit
//   - threads t<64 fill the 4x64 (cos,sin) smem table meanwhile
//   - wait_group 0 + one barrier, rotate from smem, evict-first store.

#define B_      16
#define S_      8192
#define HALF    64
#define JPOS    4
#define THREADS 256

__global__ void __launch_bounds__(THREADS) rope_apply(
    const float4* __restrict__ x, float4* __restrict__ out)
{
    __shared__ float4 sbuf[JPOS][THREADS];   // staged input (16 KB)
    __shared__ float2 s_trig[JPOS][HALF];    // (cos,sin) per pos x freq

    int t  = threadIdx.x;
    int p0 = blockIdx.x * JPOS;

    int batch = (blockIdx.y << 3) + (t >> 5);   // 0..15
    int d4    = t & 31;                         // float4 index within head dim
    size_t base = (size_t)batch * (S_ * 32) + (size_t)p0 * 32 + d4;

    // 4 independent 16B async copies per thread (no register residency)
    unsigned sa = (unsigned)__cvta_generic_to_shared(&sbuf[0][t]);
#pragma unroll
    for (int j = 0; j < JPOS; j++) {
        asm volatile("cp.async.cg.shared.global [%0], [%1], 16;"
                     :: "r"(sa + j * (THREADS * 16)),
                        "l"(&x[base + (size_t)j * 32]) : "memory");
    }
    asm volatile("cp.async.commit_group;" ::: "memory");

    // 2 warps fill the 4x64 trig table while the copies are in flight
    if (t < HALF) {
        const double LOG2_THETA = 13.287712379549449;  // log2(10000)
        float wf = (float)exp2(-((2.0 * (double)t) / 128.0) * LOG2_THETA);
#pragma unroll
        for (int j = 0; j < JPOS; j++) {
            float ang = (float)(p0 + j) * wf;
            float s, c;
            sincosf(ang, &s, &c);
            s_trig[j][t] = make_float2(c, s);
        }
    }

    asm volatile("cp.async.wait_group 0;" ::: "memory");
    __syncthreads();

#pragma unroll
    for (int j = 0; j < JPOS; j++) {
        float4 v = sbuf[j][t];
        // (cos_{2d4}, sin_{2d4}, cos_{2d4+1}, sin_{2d4+1}) via one LDS.128
        float4 cs = reinterpret_cast<const float4*>(s_trig[j])[d4];
        float4 o;
        o.x = v.x * cs.x - v.y * cs.y;
        o.y = v.x * cs.y + v.y * cs.x;
        o.z = v.z * cs.z - v.w * cs.w;
        o.w = v.z * cs.w + v.w * cs.z;
        __stcs(&out[base + (size_t)j * 32], o);
    }
}

extern "C" void kernel_launch(void* const* d_in, const int* in_sizes, int n_in,
                              void* d_out, int out_size) {
    const float4* x = (const float4*)d_in[0];
    float4* out = (float4*)d_out;

    dim3 grid(S_ / JPOS, 2);   // 2048 x 2 = 4096 blocks
    rope_apply<<<grid, THREADS>>>(x, out);
}

// round 14
// speedup vs baseline: 1.0962x; 1.0962x over previous
#include <cuda_runtime.h>
#include <cuda_bf16.h>
#include <math.h>

// RoPE: x[B=16, S=8192, D=128] fp32, interleaved pairs, pos = arange(S)
// (token_positions is ignored by the reference).
//
// Final kernel (empirical argmin over 13 tuning rounds):
//   - block = 4 positions x 8 batches x 32 float4 (256 threads, ~39 regs)
//   - front-batch 4 independent float4 loads, DEFAULT cache policy
//     (input stays partially L2-resident across graph replays; explicit
//     evict-last policies thrash or are neutral)
//   - threads t<64: wf = fp32(theta^(-t/64)) via double exp2 (matches
//     reference rounding; rel_err 4.8e-8), then 4x sincosf -> 4x64 smem
//   - one barrier, rotate via one LDS.128 per float4, evict-first store.
// Delivered: ~7.3 TB/s effective (HBM mixed-stream ceiling); occupancy,
// MLP, cp.async, persistence and cache-policy sweeps were all neutral/worse.

#define B_      16
#define S_      8192
#define HALF    64
#define JPOS    4
#define THREADS 256

__global__ void __launch_bounds__(THREADS) rope_apply(
    const float4* __restrict__ x, float4* __restrict__ out)
{
    __shared__ float2 s_trig[JPOS][HALF];   // [pos-in-block][freq] = (cos,sin)

    int t  = threadIdx.x;
    int p0 = blockIdx.x * JPOS;

    int batch = (blockIdx.y << 3) + (t >> 5);   // 0..15
    int d4    = t & 31;                         // float4 index within head dim
    size_t base = (size_t)batch * (S_ * 32) + (size_t)p0 * 32 + d4;

    // Front-batch 4 independent 16B loads (default policy: L2-cacheable)
    float4 v[JPOS];
#pragma unroll
    for (int j = 0; j < JPOS; j++)
        v[j] = __ldg(&x[base + (size_t)j * 32]);

    // 2 warps fill the 4x64 trig table while the loads are in flight
    if (t < HALF) {
        const double LOG2_THETA = 13.287712379549449;  // log2(10000)
        float wf = (float)exp2(-((2.0 * (double)t) / 128.0) * LOG2_THETA);
#pragma unroll
        for (int j = 0; j < JPOS; j++) {
            float ang = (float)(p0 + j) * wf;
            float s, c;
            sincosf(ang, &s, &c);
            s_trig[j][t] = make_float2(c, s);
        }
    }
    __syncthreads();

#pragma unroll
    for (int j = 0; j < JPOS; j++) {
        // (cos_{2d4}, sin_{2d4}, cos_{2d4+1}, sin_{2d4+1}) via one LDS.128
        float4 cs = reinterpret_cast<const float4*>(s_trig[j])[d4];
        float4 o;
        o.x = v[j].x * cs.x - v[j].y * cs.y;
        o.y = v[j].x * cs.y + v[j].y * cs.x;
        o.z = v[j].z * cs.z - v[j].w * cs.w;
        o.w = v[j].z * cs.w + v[j].w * cs.z;
        __stcs(&out[base + (size_t)j * 32], o);
    }
}

extern "C" void kernel_launch(void* const* d_in, const int* in_sizes, int n_in,
                              void* d_out, int out_size) {
    const float4* x = (const float4*)d_in[0];
    float4* out = (float4*)d_out;

    dim3 grid(S_ / JPOS, 2);   // 2048 x 2 = 4096 blocks
    rope_apply<<<grid, THREADS>>>(x, out);
}